// round 5
// baseline (speedup 1.0000x reference)
#include <cuda_runtime.h>
#include <math.h>
#include <stdint.h>

// ---------------- problem constants ----------------
#define BB    256
#define TT    512
#define SS    8
#define CD1   5        // CD+1
#define RNN_  512
#define HH    520      // RNN + S
#define H4    2080
#define EE    1024
#define DD    1040

// ---------------- LSTM partitioning ----------------
#define G       5      // batch groups (52 real batches each; last group 48 real)
#define MPAD    56     // padded batches per group (7 octets)
#define MREAL   52
#define WHCOL   (G*MPAD)   // 280, width of transposed h buffer
#define NCH     26     // h-chunks (CTAs per group)
#define CHJ     20     // h indices per chunk
#define NCOL    80     // 4*CHJ gate columns per CTA
#define KHALF   260
#define KTILE   130
#define LSTM_THREADS 288
#define LSTM_ACTIVE  280   // kt(2) * mt(7) * nt(20)

// ---------------- scratch (static __device__, no allocation) ----------------
__device__ __align__(16) float g_t1[BB * EE];
__device__ __align__(16) float g_t2[BB * EE];
__device__ __align__(16) float g_h0[BB * RNN_];
__device__ __align__(16) float g_hbuf[2][HH * WHCOL];
__device__ __align__(16) float g_last[BB * HH];
__device__ __align__(16) float g_z1[BB * DD];
__device__ __align__(16) float g_z2[BB * DD];
__device__ unsigned int g_bar[8];

// ---------------- helpers ----------------
__device__ __forceinline__ float fsig(float x) {
    return 1.f / (1.f + __expf(-x));
}
__device__ __forceinline__ float ftanh_(float x) {
    float ax = fabsf(x);
    float e = __expf(-2.f * ax);
    float r = (1.f - e) / (1.f + e);
    return x < 0.f ? -r : r;
}
__device__ __forceinline__ unsigned long long splat2(float w) {
    unsigned long long r;
    asm("mov.b64 %0, {%1, %1};" : "=l"(r) : "f"(w));
    return r;
}
__device__ __forceinline__ void unpk2(unsigned long long v, float& lo, float& hi) {
    asm("mov.b64 {%0, %1}, %2;" : "=f"(lo), "=f"(hi) : "l"(v));
}
#define FMA2(d, a, b) asm("fma.rn.f32x2 %0, %1, %2, %0;" : "+l"(d) : "l"(a), "l"(b))

// ---------------- generic tiled GEMM: C = act(A[MxK] @ B[KxN] + bias) ----------------
__global__ void gemm_bias_act(const float* __restrict__ A, const float* __restrict__ Bw,
                              const float* __restrict__ bias, float* __restrict__ C,
                              int M, int N, int K, int act)
{
    __shared__ float sA[16][64];
    __shared__ float sB[16][68];
    int tid = threadIdx.x;
    int tx = tid & 15, ty = tid >> 4;
    int row0 = blockIdx.y * 64, col0 = blockIdx.x * 64;
    float acc[4][4];
    #pragma unroll
    for (int i = 0; i < 4; i++)
        #pragma unroll
        for (int j = 0; j < 4; j++) acc[i][j] = 0.f;

    for (int k0 = 0; k0 < K; k0 += 16) {
        for (int i = tid; i < 64 * 16; i += 256) {
            int r = i >> 4, c = i & 15;
            sA[c][r] = (row0 + r < M && k0 + c < K) ? A[(size_t)(row0 + r) * K + k0 + c] : 0.f;
        }
        for (int i = tid; i < 16 * 64; i += 256) {
            int r = i >> 6, c = i & 63;
            sB[r][c] = (k0 + r < K && col0 + c < N) ? Bw[(size_t)(k0 + r) * N + col0 + c] : 0.f;
        }
        __syncthreads();
        #pragma unroll
        for (int kk = 0; kk < 16; ++kk) {
            float a[4], b[4];
            #pragma unroll
            for (int i = 0; i < 4; i++) a[i] = sA[kk][ty * 4 + i];
            #pragma unroll
            for (int j = 0; j < 4; j++) b[j] = sB[kk][tx * 4 + j];
            #pragma unroll
            for (int i = 0; i < 4; i++)
                #pragma unroll
                for (int j = 0; j < 4; j++) acc[i][j] += a[i] * b[j];
        }
        __syncthreads();
    }
    #pragma unroll
    for (int i = 0; i < 4; i++) {
        int r = row0 + ty * 4 + i;
        if (r >= M) continue;
        #pragma unroll
        for (int j = 0; j < 4; j++) {
            int c = col0 + tx * 4 + j;
            if (c >= N) continue;
            float v = acc[i][j] + bias[c];
            if (act) v = tanhf(v);
            C[(size_t)r * N + c] = v;
        }
    }
}

// ---------------- pack h0_stack transposed + zero barrier counters ----------------
__global__ void pack_h0_kernel(const float* __restrict__ x)
{
    int idx = blockIdx.x * blockDim.x + threadIdx.x;
    if (idx < 8) g_bar[idx] = 0u;
    const int total = HH * WHCOL;
    int stride = gridDim.x * blockDim.x;
    for (int i = idx; i < total; i += stride) {
        int k = i / WHCOL, col = i % WHCOL;
        int grp = col / MPAD, m = col % MPAD;
        int b = grp * MREAL + m;
        float v = 0.f;
        if (m < MREAL && b < BB)
            v = (k < SS) ? x[b * SS + k] : g_h0[b * RNN_ + (k - SS)];
        g_hbuf[0][i] = v;
    }
}

// ---------------- persistent LSTM ----------------
struct LstmSmem {
    float Ws[HH * NCOL];                 // 166400 B : W_hh slice [k][jj*4+q]
    float tile[2 * KTILE * MPAD];        // 58240 B  : h tile [half][kl][m]; reused as red area
    float Wi[CD1 * NCOL];                // 1600
    float bs[NCOL];                      // 320
    float u[MPAD * CD1];                 // 1120
    float dl[MPAD];                      // 224
    int   hl[MPAD];                      // 224
    int   mx;
};

__global__ void __launch_bounds__(LSTM_THREADS, 1)
lstm_kernel(const float* __restrict__ rnn_input, const float* __restrict__ deltas,
            const int* __restrict__ h_lens, const float* __restrict__ W_ih,
            const float* __restrict__ W_hh, const float* __restrict__ b_lstm)
{
    extern __shared__ char smem_raw[];
    LstmSmem& sm = *reinterpret_cast<LstmSmem*>(smem_raw);
    const int tid   = threadIdx.x;
    const int grp   = blockIdx.x / NCH;
    const int chunk = blockIdx.x % NCH;
    const int j0    = chunk * CHJ;
    const int mb0   = grp * MPAD;   // column base in g_hbuf
    const int bb0   = grp * MREAL;  // real batch base

    // ---- one-time loads: weight slice resident in SMEM ----
    for (int i = tid; i < HH * NCOL; i += LSTM_THREADS) {
        int k = i / NCOL, n = i % NCOL;
        int jj = n >> 2, q = n & 3;
        sm.Ws[i] = W_hh[(size_t)k * H4 + q * HH + j0 + jj];
    }
    for (int i = tid; i < CD1 * NCOL; i += LSTM_THREADS) {
        int c = i / NCOL, n = i % NCOL;
        int jj = n >> 2, q = n & 3;
        sm.Wi[i] = W_ih[(size_t)c * H4 + q * HH + j0 + jj];
    }
    for (int i = tid; i < NCOL; i += LSTM_THREADS) {
        int jj = i >> 2, q = i & 3;
        sm.bs[i] = b_lstm[q * HH + j0 + jj];
    }
    for (int i = tid; i < MPAD; i += LSTM_THREADS) {
        int b = bb0 + i;
        sm.hl[i] = (i < MREAL && b < BB) ? h_lens[b] : 0;
    }
    __syncthreads();
    if (tid == 0) {
        int mx = 1;
        for (int m = 0; m < MPAD; ++m) mx = max(mx, sm.hl[m]);
        sm.mx = mx;
    }
    __syncthreads();
    const int maxlen = sm.mx;

    const bool active = tid < LSTM_ACTIVE;
    const int k_id = tid / 140;      // K-half 0/1
    const int rem  = tid % 140;
    const int m_id = rem / CHJ;      // batch octet 0..6
    const int jj   = rem % CHJ;      // h index within chunk 0..19
    const int m0t  = m_id * 8;

    float creg[8], hreg[8];
    #pragma unroll
    for (int i = 0; i < 8; i++) { creg[i] = 0.f; hreg[i] = 0.f; }
    if (active && k_id == 0) {
        #pragma unroll
        for (int i = 0; i < 8; i++)
            hreg[i] = g_hbuf[0][(j0 + jj) * WHCOL + mb0 + m0t + i];
    }

    float* redf = sm.tile;   // alias for reduction area

    for (int s = 0; s < maxlen; ++s) {
        // ---- per-step inputs into SMEM ----
        if (tid < MPAD * CD1) {
            int m = tid / CD1, c = tid % CD1, b = bb0 + m;
            sm.u[tid] = (m < MREAL && b < BB) ? rnn_input[((size_t)b * TT + s) * CD1 + c] : 0.f;
        }
        if (tid < MPAD) {
            int b = bb0 + tid;
            sm.dl[tid] = (tid < MREAL && b < BB) ? deltas[(size_t)b * TT + s] : 0.f;
        }
        const float* __restrict__ hsrc = g_hbuf[s & 1];
        float* __restrict__ hdst = g_hbuf[(s & 1) ^ 1];

        unsigned long long acc[4][4];
        #pragma unroll
        for (int q = 0; q < 4; q++)
            #pragma unroll
            for (int pr = 0; pr < 4; pr++) acc[q][pr] = 0ull;

        // ---- two phases, each loads a 130-row K-tile for BOTH halves ----
        #pragma unroll 1
        for (int p = 0; p < 2; ++p) {
            __syncthreads();  // prior tile fully consumed
            // load tiles (both halves) [2][130][56] as float4
            for (int i = tid; i < 2 * KTILE * (MPAD / 4); i += LSTM_THREADS) {
                int half = i / (KTILE * 14);
                int r = i % (KTILE * 14);
                int kl = r / 14, q4 = r % 14;
                int k = half * KHALF + p * KTILE + kl;
                float4 v = __ldcg((const float4*)&hsrc[k * WHCOL + mb0 + q4 * 4]);
                *(float4*)&sm.tile[(half * KTILE + kl) * MPAD + q4 * 4] = v;
            }
            __syncthreads();
            if (active) {
                const float* hb = &sm.tile[(k_id * KTILE) * MPAD + m0t];
                const float4* wb = (const float4*)&sm.Ws[(k_id * KHALF + p * KTILE) * NCOL + jj * 4];
                #pragma unroll 2
                for (int kl = 0; kl < KTILE; ++kl) {
                    float4 w = wb[kl * (NCOL / 4)];
                    const unsigned long long* hp =
                        (const unsigned long long*)(hb + kl * MPAD);
                    unsigned long long h0v = hp[0], h1v = hp[1], h2v = hp[2], h3v = hp[3];
                    unsigned long long wi = splat2(w.x), wf = splat2(w.y),
                                       wg = splat2(w.z), wo = splat2(w.w);
                    FMA2(acc[0][0], wi, h0v); FMA2(acc[0][1], wi, h1v);
                    FMA2(acc[0][2], wi, h2v); FMA2(acc[0][3], wi, h3v);
                    FMA2(acc[1][0], wf, h0v); FMA2(acc[1][1], wf, h1v);
                    FMA2(acc[1][2], wf, h2v); FMA2(acc[1][3], wf, h3v);
                    FMA2(acc[2][0], wg, h0v); FMA2(acc[2][1], wg, h1v);
                    FMA2(acc[2][2], wg, h2v); FMA2(acc[2][3], wg, h3v);
                    FMA2(acc[3][0], wo, h0v); FMA2(acc[3][1], wo, h1v);
                    FMA2(acc[3][2], wo, h2v); FMA2(acc[3][3], wo, h3v);
                }
            }
        }

        // ---- cross-k reduction via SMEM (tile area reused) ----
        __syncthreads();
        if (active && k_id == 1) {
            float* rp = &redf[(m_id * CHJ + jj) * 32];
            #pragma unroll
            for (int q = 0; q < 4; q++)
                #pragma unroll
                for (int pr = 0; pr < 4; pr++) {
                    float lo, hi;
                    unpk2(acc[q][pr], lo, hi);
                    rp[q * 8 + 2 * pr]     = lo;
                    rp[q * 8 + 2 * pr + 1] = hi;
                }
        }
        __syncthreads();

        // ---- epilogue: gates, activations, state update, last capture ----
        if (active && k_id == 0) {
            float gv[4][8];
            const float* rp = &redf[(m_id * CHJ + jj) * 32];
            #pragma unroll
            for (int q = 0; q < 4; q++) {
                #pragma unroll
                for (int pr = 0; pr < 4; pr++) {
                    float lo, hi;
                    unpk2(acc[q][pr], lo, hi);
                    gv[q][2 * pr]     = lo + rp[q * 8 + 2 * pr];
                    gv[q][2 * pr + 1] = hi + rp[q * 8 + 2 * pr + 1];
                }
            }
            #pragma unroll
            for (int i = 0; i < 8; ++i) {
                int m = m0t + i;
                float ui = sm.bs[jj * 4 + 0], uf = sm.bs[jj * 4 + 1];
                float ug = sm.bs[jj * 4 + 2], uo = sm.bs[jj * 4 + 3];
                #pragma unroll
                for (int c = 0; c < CD1; ++c) {
                    float uv = sm.u[m * CD1 + c];
                    const float* wr = &sm.Wi[c * NCOL + jj * 4];
                    ui += uv * wr[0]; uf += uv * wr[1];
                    ug += uv * wr[2]; uo += uv * wr[3];
                }
                float zi = gv[0][i] + ui;
                float zf = gv[1][i] + uf;
                float zg = gv[2][i] + ug;
                float zo = gv[3][i] + uo;
                float cn = fsig(zf) * creg[i] + fsig(zi) * ftanh_(zg);
                float hn = fsig(zo) * ftanh_(cn);
                int len = sm.hl[m];
                if (s < len) {
                    if (s == len - 1) {
                        float d = sm.dl[m];
                        int b = bb0 + m;
                        g_last[(size_t)b * HH + (j0 + jj)] =
                            (1.f - d) * hreg[i] + d * hn;
                    }
                    creg[i] = cn;
                    hreg[i] = hn;
                }
            }
            // publish h (unchanged rows too — next step reads full buffer)
            float4 v0 = make_float4(hreg[0], hreg[1], hreg[2], hreg[3]);
            float4 v1 = make_float4(hreg[4], hreg[5], hreg[6], hreg[7]);
            float* dp = &hdst[(j0 + jj) * WHCOL + mb0 + m0t];
            __stcg((float4*)dp, v0);
            __stcg((float4*)(dp + 4), v1);
        }

        // ---- per-group global barrier (130 CTAs resident: deadlock-free) ----
        __syncthreads();
        if (tid == 0) {
            __threadfence();
            atomicAdd(&g_bar[grp], 1u);
            unsigned int target = (unsigned int)(s + 1) * NCH;
            while (atomicAdd(&g_bar[grp], 0u) < target) { }
            __threadfence();
        }
        __syncthreads();
    }
}

// ---------------- launch ----------------
extern "C" void kernel_launch(void* const* d_in, const int* in_sizes, int n_in,
                              void* d_out, int out_size)
{
    (void)in_sizes; (void)n_in;
    const float* x        = (const float*)d_in[0];
    const float* rnn_in   = (const float*)d_in[1];
    const float* deltas   = (const float*)d_in[2];
    const int*   h_lens   = (const int*)d_in[3];
    const float* enc_w1   = (const float*)d_in[4];
    const float* enc_b1   = (const float*)d_in[5];
    const float* enc_w2   = (const float*)d_in[6];
    const float* enc_b2   = (const float*)d_in[7];
    const float* enc_w3   = (const float*)d_in[8];
    const float* enc_b3   = (const float*)d_in[9];
    const float* W_ih     = (const float*)d_in[10];
    const float* W_hh     = (const float*)d_in[11];
    const float* b_lstm   = (const float*)d_in[12];
    const float* dec_w1   = (const float*)d_in[13];
    const float* dec_b1   = (const float*)d_in[14];
    const float* dec_w2   = (const float*)d_in[15];
    const float* dec_b2   = (const float*)d_in[16];
    const float* dec_w3   = (const float*)d_in[17];
    const float* dec_b3   = (const float*)d_in[18];
    float* out = (float*)d_out;
    (void)out_size;

    float *t1, *t2, *h0, *last, *z1, *z2;
    cudaGetSymbolAddress((void**)&t1,   g_t1);
    cudaGetSymbolAddress((void**)&t2,   g_t2);
    cudaGetSymbolAddress((void**)&h0,   g_h0);
    cudaGetSymbolAddress((void**)&last, g_last);
    cudaGetSymbolAddress((void**)&z1,   g_z1);
    cudaGetSymbolAddress((void**)&z2,   g_z2);

    // encoder
    gemm_bias_act<<<dim3(EE / 64, BB / 64), 256>>>(x,  enc_w1, enc_b1, t1, BB, EE,  SS,  1);
    gemm_bias_act<<<dim3(EE / 64, BB / 64), 256>>>(t1, enc_w2, enc_b2, t2, BB, EE,  EE,  1);
    gemm_bias_act<<<dim3(RNN_ / 64, BB / 64), 256>>>(t2, enc_w3, enc_b3, h0, BB, RNN_, EE, 0);

    // pack transposed h0_stack + reset barriers
    pack_h0_kernel<<<120, 256>>>(x);

    // persistent LSTM
    static_assert(sizeof(LstmSmem) <= 232448, "smem over limit");
    cudaFuncSetAttribute(lstm_kernel, cudaFuncAttributeMaxDynamicSharedMemorySize,
                         (int)sizeof(LstmSmem));
    lstm_kernel<<<G * NCH, LSTM_THREADS, sizeof(LstmSmem)>>>(
        rnn_in, deltas, h_lens, W_ih, W_hh, b_lstm);

    // decoder
    gemm_bias_act<<<dim3((DD + 63) / 64, BB / 64), 256>>>(last, dec_w1, dec_b1, z1, BB, DD, HH, 1);
    gemm_bias_act<<<dim3((DD + 63) / 64, BB / 64), 256>>>(z1,   dec_w2, dec_b2, z2, BB, DD, DD, 1);
    gemm_bias_act<<<dim3(1, BB / 64), 256>>>(z2, dec_w3, dec_b3, out, BB, SS, DD, 0);
}

// round 6
// speedup vs baseline: 1.2716x; 1.2716x over previous
#include <cuda_runtime.h>
#include <math.h>
#include <stdint.h>

// ---------------- problem constants ----------------
#define BB    256
#define TT    512
#define SS    8
#define CD1   5        // CD+1
#define RNN_  512
#define HH    520      // RNN + S
#define H4    2080
#define EE    1024
#define DD    1040

// ---------------- LSTM partitioning ----------------
#define G       6      // batch groups (43 real each; last 41)
#define MREAL   43
#define MPAD    44     // padded batches per group (11 quads)
#define WHCOL   (G*MPAD)   // 264, width of transposed h buffer
#define NCH     24     // h-chunks (CTAs per group) -> 144 CTAs total
#define CHJ     22     // h indices per chunk (24*22=528 >= 520, tail guarded)
#define NCOL    88     // 4*CHJ gate columns per CTA
#define KTILE   130
#define NPH     4      // 4*130 = 520
#define THREADS 256
#define ACTIVE  242    // 11 batch-quads * 22 jj

// ---------------- scratch (static __device__, no allocation) ----------------
__device__ __align__(16) float g_t1[BB * EE];
__device__ __align__(16) float g_t2[BB * EE];
__device__ __align__(16) float g_h0[BB * RNN_];
__device__ __align__(16) float g_hbuf[2][HH * WHCOL];
__device__ __align__(16) float g_last[BB * HH];
__device__ __align__(16) float g_z1[BB * DD];
__device__ __align__(16) float g_z2[BB * DD];
__device__ unsigned int g_bar[8];

// ---------------- helpers ----------------
__device__ __forceinline__ float fsig(float x) {
    return 1.f / (1.f + __expf(-x));
}
__device__ __forceinline__ float ftanh_(float x) {
    float ax = fabsf(x);
    float e = __expf(-2.f * ax);
    float r = (1.f - e) / (1.f + e);
    return x < 0.f ? -r : r;
}
__device__ __forceinline__ unsigned long long splat2(float w) {
    unsigned long long r;
    asm("mov.b64 %0, {%1, %1};" : "=l"(r) : "f"(w));
    return r;
}
__device__ __forceinline__ void unpk2(unsigned long long v, float& lo, float& hi) {
    asm("mov.b64 {%0, %1}, %2;" : "=f"(lo), "=f"(hi) : "l"(v));
}
#define FMA2(d, a, b) asm("fma.rn.f32x2 %0, %1, %2, %0;" : "+l"(d) : "l"(a), "l"(b))

__device__ __forceinline__ void cp16(uint32_t saddr, const void* gaddr) {
    asm volatile("cp.async.cg.shared.global [%0], [%1], 16;"
                 :: "r"(saddr), "l"(gaddr));
}

// ---------------- generic tiled GEMM: C = act(A[MxK] @ B[KxN] + bias) ----------------
__global__ void gemm_bias_act(const float* __restrict__ A, const float* __restrict__ Bw,
                              const float* __restrict__ bias, float* __restrict__ C,
                              int M, int N, int K, int act)
{
    __shared__ float sA[16][64];
    __shared__ float sB[16][68];
    int tid = threadIdx.x;
    int tx = tid & 15, ty = tid >> 4;
    int row0 = blockIdx.y * 64, col0 = blockIdx.x * 64;
    float acc[4][4];
    #pragma unroll
    for (int i = 0; i < 4; i++)
        #pragma unroll
        for (int j = 0; j < 4; j++) acc[i][j] = 0.f;

    for (int k0 = 0; k0 < K; k0 += 16) {
        for (int i = tid; i < 64 * 16; i += 256) {
            int r = i >> 4, c = i & 15;
            sA[c][r] = (row0 + r < M && k0 + c < K) ? A[(size_t)(row0 + r) * K + k0 + c] : 0.f;
        }
        for (int i = tid; i < 16 * 64; i += 256) {
            int r = i >> 6, c = i & 63;
            sB[r][c] = (k0 + r < K && col0 + c < N) ? Bw[(size_t)(k0 + r) * N + col0 + c] : 0.f;
        }
        __syncthreads();
        #pragma unroll
        for (int kk = 0; kk < 16; ++kk) {
            float a[4], b[4];
            #pragma unroll
            for (int i = 0; i < 4; i++) a[i] = sA[kk][ty * 4 + i];
            #pragma unroll
            for (int j = 0; j < 4; j++) b[j] = sB[kk][tx * 4 + j];
            #pragma unroll
            for (int i = 0; i < 4; i++)
                #pragma unroll
                for (int j = 0; j < 4; j++) acc[i][j] += a[i] * b[j];
        }
        __syncthreads();
    }
    #pragma unroll
    for (int i = 0; i < 4; i++) {
        int r = row0 + ty * 4 + i;
        if (r >= M) continue;
        #pragma unroll
        for (int j = 0; j < 4; j++) {
            int c = col0 + tx * 4 + j;
            if (c >= N) continue;
            float v = acc[i][j] + bias[c];
            if (act) v = tanhf(v);
            C[(size_t)r * N + c] = v;
        }
    }
}

// ---------------- pack h0_stack transposed + zero barrier counters ----------------
__global__ void pack_h0_kernel(const float* __restrict__ x)
{
    int idx = blockIdx.x * blockDim.x + threadIdx.x;
    if (idx < 8) g_bar[idx] = 0u;
    const int total = HH * WHCOL;
    int stride = gridDim.x * blockDim.x;
    for (int i = idx; i < total; i += stride) {
        int k = i / WHCOL, col = i % WHCOL;
        int grp = col / MPAD, m = col % MPAD;
        int b = grp * MREAL + m;
        float v = 0.f;
        if (m < MREAL && b < BB)
            v = (k < SS) ? x[b * SS + k] : g_h0[b * RNN_ + (k - SS)];
        g_hbuf[0][i] = v;
    }
}

// ---------------- persistent LSTM ----------------
struct LstmSmem {
    float Ws[HH * NCOL];             // 183040 B : W_hh slice [k][jj*4+q]
    float tile[2][KTILE * MPAD];     // 45760 B  : double-buffered h tiles [kl][m]
    float Wi[CD1 * NCOL];            // 1760
    float bs[NCOL];                  // 352
    float u[MPAD * CD1];             // 880
    float dl[MPAD];                  // 176
    int   hl[MPAD];                  // 176
    int   mx;                        // 4
};
static_assert(sizeof(LstmSmem) <= 232448, "smem over limit");

__global__ void __launch_bounds__(THREADS, 1)
lstm_kernel(const float* __restrict__ rnn_input, const float* __restrict__ deltas,
            const int* __restrict__ h_lens, const float* __restrict__ W_ih,
            const float* __restrict__ W_hh, const float* __restrict__ b_lstm)
{
    extern __shared__ char smem_raw[];
    LstmSmem& sm = *reinterpret_cast<LstmSmem*>(smem_raw);
    const int tid   = threadIdx.x;
    const int grp   = blockIdx.x / NCH;
    const int chunk = blockIdx.x % NCH;
    const int j0    = chunk * CHJ;
    const int mb0   = grp * MPAD;   // column base in g_hbuf
    const int bb0   = grp * MREAL;  // real batch base

    // ---- one-time loads: weight slice resident in SMEM ----
    for (int i = tid; i < HH * NCOL; i += THREADS) {
        int k = i / NCOL, n = i % NCOL;
        int jj = n >> 2, q = n & 3;
        int j = j0 + jj;
        sm.Ws[i] = (j < HH) ? W_hh[(size_t)k * H4 + q * HH + j] : 0.f;
    }
    for (int i = tid; i < CD1 * NCOL; i += THREADS) {
        int c = i / NCOL, n = i % NCOL;
        int jj = n >> 2, q = n & 3;
        int j = j0 + jj;
        sm.Wi[i] = (j < HH) ? W_ih[(size_t)c * H4 + q * HH + j] : 0.f;
    }
    for (int i = tid; i < NCOL; i += THREADS) {
        int jj = i >> 2, q = i & 3;
        int j = j0 + jj;
        sm.bs[i] = (j < HH) ? b_lstm[q * HH + j] : 0.f;
    }
    for (int i = tid; i < MPAD; i += THREADS) {
        int b = bb0 + i;
        sm.hl[i] = (i < MREAL && b < BB) ? h_lens[b] : 0;
    }
    __syncthreads();
    if (tid == 0) {
        int mx = 1;
        for (int m = 0; m < MPAD; ++m) mx = max(mx, sm.hl[m]);
        sm.mx = mx;
    }
    __syncthreads();
    const int maxlen = sm.mx;

    const bool act = tid < ACTIVE;
    const int mq = tid / CHJ;        // batch quad 0..10
    const int jj = tid % CHJ;        // h index within chunk 0..21
    const int jg = j0 + jj;
    const bool jok = act && (jg < HH);
    const int m0 = mq * 4;

    float creg[4] = {0.f, 0.f, 0.f, 0.f};
    float hreg[4] = {0.f, 0.f, 0.f, 0.f};
    if (jok) {
        #pragma unroll
        for (int i = 0; i < 4; i++)
            hreg[i] = g_hbuf[0][(size_t)jg * WHCOL + mb0 + m0 + i];
    }

    uint32_t tile_s[2];
    tile_s[0] = (uint32_t)__cvta_generic_to_shared(&sm.tile[0][0]);
    tile_s[1] = (uint32_t)__cvta_generic_to_shared(&sm.tile[1][0]);

    // prefetch step-0 inputs into registers
    float ureg = 0.f, dreg = 0.f;
    if (tid < MPAD * CD1) {
        int m = tid / CD1, c = tid % CD1, b = bb0 + m;
        if (m < MREAL && b < BB) ureg = rnn_input[(size_t)b * TT * CD1 + c];
    }
    if (tid < MPAD) {
        int b = bb0 + tid;
        if (tid < MREAL && b < BB) dreg = deltas[(size_t)b * TT];
    }

    for (int s = 0; s < maxlen; ++s) {
        if (tid < MPAD * CD1) sm.u[tid] = ureg;
        if (tid < MPAD) sm.dl[tid] = dreg;

        const float* __restrict__ hsrc = g_hbuf[s & 1];
        float* __restrict__ hdst = g_hbuf[(s & 1) ^ 1];
        const float* __restrict__ hbase = hsrc + mb0;

        // issue tile 0 (the only exposed load of the step)
        for (int i = tid; i < KTILE * (MPAD / 4); i += THREADS) {
            int kl = i / (MPAD / 4), q4 = i % (MPAD / 4);
            cp16(tile_s[0] + (uint32_t)(kl * MPAD + q4 * 4) * 4,
                 hbase + (size_t)kl * WHCOL + q4 * 4);
        }
        asm volatile("cp.async.commit_group;");

        unsigned long long a00 = 0, a01 = 0, a10 = 0, a11 = 0,
                           a20 = 0, a21 = 0, a30 = 0, a31 = 0;

        #pragma unroll
        for (int p = 0; p < NPH; ++p) {
            asm volatile("cp.async.wait_group 0;");   // only one group in flight
            __syncthreads();                          // tile p visible; buf[(p+1)&1] free
            if (p < NPH - 1) {
                const float* src = hbase + (size_t)(p + 1) * KTILE * WHCOL;
                uint32_t dst = tile_s[(p + 1) & 1];
                for (int i = tid; i < KTILE * (MPAD / 4); i += THREADS) {
                    int kl = i / (MPAD / 4), q4 = i % (MPAD / 4);
                    cp16(dst + (uint32_t)(kl * MPAD + q4 * 4) * 4,
                         src + (size_t)kl * WHCOL + q4 * 4);
                }
                asm volatile("cp.async.commit_group;");
            }
            if (act) {
                const float* hb = &sm.tile[p & 1][m0];
                const float4* wb = (const float4*)sm.Ws + (size_t)(p * KTILE) * (NCOL / 4) + jj;
                #pragma unroll 2
                for (int kl = 0; kl < KTILE; ++kl) {
                    float4 w = wb[kl * (NCOL / 4)];
                    unsigned long long h01 = *(const unsigned long long*)(hb + kl * MPAD);
                    unsigned long long h23 = *(const unsigned long long*)(hb + kl * MPAD + 2);
                    unsigned long long wi = splat2(w.x), wf = splat2(w.y),
                                       wg = splat2(w.z), wo = splat2(w.w);
                    FMA2(a00, wi, h01); FMA2(a01, wi, h23);
                    FMA2(a10, wf, h01); FMA2(a11, wf, h23);
                    FMA2(a20, wg, h01); FMA2(a21, wg, h23);
                    FMA2(a30, wo, h01); FMA2(a31, wo, h23);
                }
            }
        }

        // ---- epilogue: gates, activations, state update, last capture ----
        if (jok) {
            float gi[4], gf[4], gg[4], go[4];
            unpk2(a00, gi[0], gi[1]); unpk2(a01, gi[2], gi[3]);
            unpk2(a10, gf[0], gf[1]); unpk2(a11, gf[2], gf[3]);
            unpk2(a20, gg[0], gg[1]); unpk2(a21, gg[2], gg[3]);
            unpk2(a30, go[0], go[1]); unpk2(a31, go[2], go[3]);
            float b0 = sm.bs[jj * 4 + 0], b1 = sm.bs[jj * 4 + 1];
            float b2 = sm.bs[jj * 4 + 2], b3 = sm.bs[jj * 4 + 3];
            #pragma unroll
            for (int i = 0; i < 4; ++i) {
                int m = m0 + i;
                float zi = gi[i] + b0, zf = gf[i] + b1;
                float zg = gg[i] + b2, zo = go[i] + b3;
                #pragma unroll
                for (int c = 0; c < CD1; ++c) {
                    float uv = sm.u[m * CD1 + c];
                    const float* wr = &sm.Wi[c * NCOL + jj * 4];
                    zi += uv * wr[0]; zf += uv * wr[1];
                    zg += uv * wr[2]; zo += uv * wr[3];
                }
                float cn = fsig(zf) * creg[i] + fsig(zi) * ftanh_(zg);
                float hn = fsig(zo) * ftanh_(cn);
                int len = sm.hl[m];
                if (s < len) {
                    if (s == len - 1) {
                        float d = sm.dl[m];
                        g_last[(size_t)(bb0 + m) * HH + jg] =
                            (1.f - d) * hreg[i] + d * hn;
                    }
                    creg[i] = cn;
                    hreg[i] = hn;
                }
            }
            float4 v = make_float4(hreg[0], hreg[1], hreg[2], hreg[3]);
            __stcg((float4*)&hdst[(size_t)jg * WHCOL + mb0 + m0], v);
        }

        // prefetch next-step inputs into registers (overlaps barrier wait)
        if (s + 1 < TT) {
            if (tid < MPAD * CD1) {
                int m = tid / CD1, c = tid % CD1, b = bb0 + m;
                if (m < MREAL && b < BB)
                    ureg = rnn_input[((size_t)b * TT + s + 1) * CD1 + c];
            }
            if (tid < MPAD) {
                int b = bb0 + tid;
                if (tid < MREAL && b < BB)
                    dreg = deltas[(size_t)b * TT + s + 1];
            }
        }

        // ---- per-group global barrier (144 CTAs resident: single wave, safe) ----
        __threadfence();        // release: every storing thread fences its own STGs
        __syncthreads();
        if (tid == 0) {
            atomicAdd(&g_bar[grp], 1u);
            unsigned int target = (unsigned int)(s + 1) * NCH;
            while (*(volatile unsigned int*)&g_bar[grp] < target) { }
            __threadfence();    // acquire
        }
        __syncthreads();
    }
}

// ---------------- launch ----------------
extern "C" void kernel_launch(void* const* d_in, const int* in_sizes, int n_in,
                              void* d_out, int out_size)
{
    (void)in_sizes; (void)n_in; (void)out_size;
    const float* x        = (const float*)d_in[0];
    const float* rnn_in   = (const float*)d_in[1];
    const float* deltas   = (const float*)d_in[2];
    const int*   h_lens   = (const int*)d_in[3];
    const float* enc_w1   = (const float*)d_in[4];
    const float* enc_b1   = (const float*)d_in[5];
    const float* enc_w2   = (const float*)d_in[6];
    const float* enc_b2   = (const float*)d_in[7];
    const float* enc_w3   = (const float*)d_in[8];
    const float* enc_b3   = (const float*)d_in[9];
    const float* W_ih     = (const float*)d_in[10];
    const float* W_hh     = (const float*)d_in[11];
    const float* b_lstm   = (const float*)d_in[12];
    const float* dec_w1   = (const float*)d_in[13];
    const float* dec_b1   = (const float*)d_in[14];
    const float* dec_w2   = (const float*)d_in[15];
    const float* dec_b2   = (const float*)d_in[16];
    const float* dec_w3   = (const float*)d_in[17];
    const float* dec_b3   = (const float*)d_in[18];
    float* out = (float*)d_out;

    float *t1, *t2, *h0, *last, *z1, *z2;
    cudaGetSymbolAddress((void**)&t1,   g_t1);
    cudaGetSymbolAddress((void**)&t2,   g_t2);
    cudaGetSymbolAddress((void**)&h0,   g_h0);
    cudaGetSymbolAddress((void**)&last, g_last);
    cudaGetSymbolAddress((void**)&z1,   g_z1);
    cudaGetSymbolAddress((void**)&z2,   g_z2);

    // encoder
    gemm_bias_act<<<dim3(EE / 64, BB / 64), 256>>>(x,  enc_w1, enc_b1, t1, BB, EE,  SS,  1);
    gemm_bias_act<<<dim3(EE / 64, BB / 64), 256>>>(t1, enc_w2, enc_b2, t2, BB, EE,  EE,  1);
    gemm_bias_act<<<dim3(RNN_ / 64, BB / 64), 256>>>(t2, enc_w3, enc_b3, h0, BB, RNN_, EE, 0);

    // pack transposed h0_stack + reset barriers
    pack_h0_kernel<<<120, 256>>>(x);

    // persistent LSTM
    cudaFuncSetAttribute(lstm_kernel, cudaFuncAttributeMaxDynamicSharedMemorySize,
                         (int)sizeof(LstmSmem));
    lstm_kernel<<<G * NCH, THREADS, sizeof(LstmSmem)>>>(
        rnn_in, deltas, h_lens, W_ih, W_hh, b_lstm);

    // decoder
    gemm_bias_act<<<dim3((DD + 63) / 64, BB / 64), 256>>>(last, dec_w1, dec_b1, z1, BB, DD, HH, 1);
    gemm_bias_act<<<dim3((DD + 63) / 64, BB / 64), 256>>>(z1,   dec_w2, dec_b2, z2, BB, DD, DD, 1);
    gemm_bias_act<<<dim3(1, BB / 64), 256>>>(z2, dec_w3, dec_b3, out, BB, SS, DD, 0);
}